// round 9
// baseline (speedup 1.0000x reference)
#include <cuda_runtime.h>
#include <math.h>

// ---------------- scratch (__device__ globals; no allocations) ----------------
__device__ float g_x0 [4*16*32*32];
__device__ float g_xa [4*4*64*64];
__device__ float g_xb [4*4*128*128];
__device__ float g_xc [4*4*256*256];
__device__ float g_g64 [4*3*64*64];
__device__ float g_g128[4*3*128*128];
__device__ float g_g256[4*3*256*256];

// ============================================================================
// PREP: 1x1 conv (384->16)+leaky fused with all 3 guide resizes.
// ============================================================================
__device__ __forceinline__ void resize_scalar(
    const float* __restrict__ g, float* __restrict__ out, int OH, int f, int idx)
{
    if (idx >= 4*3*OH*OH) return;
    int ow = idx % OH;
    int t  = idx / OH;
    int oh = t % OH;
    int pl = t / OH;
    const float* gp = g + pl*512*512;
    const float* r0 = gp + (f*oh + (f>>1) - 1)*512 + (f*ow + (f>>1) - 1);
    out[idx] = 0.25f*(r0[0] + r0[1] + r0[512] + r0[513]);
}

__global__ __launch_bounds__(256) void prep_kernel(
    const float* __restrict__ x, const float* __restrict__ lw,
    const float* __restrict__ lb, const float* __restrict__ guide,
    float* __restrict__ x0,
    float* __restrict__ o256, float* __restrict__ o128, float* __restrict__ o64)
{
    const int bid = blockIdx.x;
    const int tid = threadIdx.x;

    if (bid < 64) {
        __shared__ float sw[16*384];
        for (int i = tid; i < 16*384; i += 256) sw[i] = lw[i];
        __syncthreads();
        const int pix = bid*64 + (tid & 63);
        const int b   = pix >> 10;
        const int hw  = pix & 1023;
        const int o0  = (tid >> 6) * 4;
        const float* xp  = x + b*384*1024 + hw;
        const float* w0p = sw + (o0+0)*384;
        const float* w1p = sw + (o0+1)*384;
        const float* w2p = sw + (o0+2)*384;
        const float* w3p = sw + (o0+3)*384;
        float a0=0.f, a1=0.f, a2=0.f, a3=0.f;
        #pragma unroll 4
        for (int i = 0; i < 384; ++i) {
            float xv = xp[i*1024];
            a0 += w0p[i]*xv; a1 += w1p[i]*xv; a2 += w2p[i]*xv; a3 += w3p[i]*xv;
        }
        a0 += lb[o0+0]; a1 += lb[o0+1]; a2 += lb[o0+2]; a3 += lb[o0+3];
        a0 = (a0 >= 0.f) ? a0 : 0.01f*a0;
        a1 = (a1 >= 0.f) ? a1 : 0.01f*a1;
        a2 = (a2 >= 0.f) ? a2 : 0.01f*a2;
        a3 = (a3 >= 0.f) ? a3 : 0.01f*a3;
        float* op = x0 + (b*16 + o0)*1024 + hw;
        op[0] = a0; op[1024] = a1; op[2048] = a2; op[3072] = a3;
    } else if (bid < 832) {
        int idx = (bid - 64)*256 + tid;
        int ow4 = idx & 63;
        int t   = idx >> 6;
        int oh  = t & 255;
        int pl  = t >> 8;
        const float* gp = guide + pl*512*512 + (2*oh)*512 + ow4*8;
        float4 a = ((const float4*)gp)[0];
        float4 b4 = ((const float4*)gp)[1];
        float4 c = ((const float4*)(gp + 512))[0];
        float4 d = ((const float4*)(gp + 512))[1];
        float4 r;
        r.x = 0.25f*(a.x + a.y + c.x + c.y);
        r.y = 0.25f*(a.z + a.w + c.z + c.w);
        r.z = 0.25f*(b4.x + b4.y + d.x + d.y);
        r.w = 0.25f*(b4.z + b4.w + d.z + d.w);
        ((float4*)o256)[idx] = r;
    } else if (bid < 1600) {
        resize_scalar(guide, o128, 128, 4, (bid - 832)*256 + tid);
    } else {
        resize_scalar(guide, o64,   64, 8, (bid - 1600)*256 + tid);
    }
}

// ============================================================================
// pac_tile: CI=16 stage (64x64 only, small)
// ============================================================================
#define TW 32
#define TH 8
#define GP (TW+2)
#define GTILE ((TH+2)*GP)
#define XP (TW/2+2)
#define XTILE ((TH/2+2)*XP)

template<int CI, int CO>
__global__ __launch_bounds__(256) void pac_tile(
    const float* __restrict__ xin, const float* __restrict__ gd,
    const float* __restrict__ wt, float* __restrict__ out,
    int H, int W)
{
    constexpr int NC4 = CI/4;
    __shared__ float4 sg[GTILE];
    __shared__ float4 sx[XTILE*NC4];
    __shared__ float4 swt[9*CO*NC4];

    const int tid = threadIdx.x;
    const int b   = blockIdx.z;
    const int h0  = blockIdx.y * TH;
    const int w0  = blockIdx.x * TW;
    const int HW  = H*W;
    const int H2 = H >> 1, W2 = W >> 1, HW2 = H2*W2;

    const float* gb = gd + b*3*HW;
    for (int i = tid; i < GTILE; i += 256) {
        int r = i / GP, q = i - r*GP;
        int gh = h0 - 1 + r, gw = w0 - 1 + q;
        float4 v;
        if ((gh >= 0) & (gh < H) & (gw >= 0) & (gw < W)) {
            int off = gh*W + gw;
            v.x = gb[off]; v.y = gb[HW + off]; v.z = gb[2*HW + off];
        } else { v.x = v.y = v.z = 1e19f; }
        v.w = 0.f;
        sg[i] = v;
    }
    const float* xb = xin + b*CI*HW2;
    for (int i = tid; i < XTILE*NC4; i += 256) {
        int pos = i / NC4, c4 = i - pos*NC4;
        int r = pos / XP, q = pos - r*XP;
        int xh = (h0>>1) - 1 + r, xw = (w0>>1) - 1 + q;
        float4 v = make_float4(0.f, 0.f, 0.f, 0.f);
        if ((xh >= 0) & (xh < H2) & (xw >= 0) & (xw < W2)) {
            int off = xh*W2 + xw;
            const float* p = xb + (c4*4)*HW2 + off;
            v.x = p[0]; v.y = p[HW2]; v.z = p[2*HW2]; v.w = p[3*HW2];
        }
        sx[i] = v;
    }
    for (int i = tid; i < 9*CO*NC4; i += 256) {
        int c4 = i % NC4;
        int t2 = i / NC4;
        int o  = t2 % CO;
        int k  = t2 / CO;
        float4 v;
        v.x = wt[(o*CI + c4*4 + 0)*9 + k];
        v.y = wt[(o*CI + c4*4 + 1)*9 + k];
        v.z = wt[(o*CI + c4*4 + 2)*9 + k];
        v.w = wt[(o*CI + c4*4 + 3)*9 + k];
        swt[i] = v;
    }
    __syncthreads();

    const int ty = tid >> 5, tx = tid & 31;
    const int gi0 = (ty+1)*GP + (tx+1);
    const float4 gc = sg[gi0];

    float acc[CO];
    #pragma unroll
    for (int o = 0; o < CO; ++o) acc[o] = 0.f;

    #pragma unroll
    for (int k = 0; k < 9; ++k) {
        const int di = k/3 - 1, dj = k%3 - 1;
        float4 g4 = sg[gi0 + di*GP + dj];
        float d0 = g4.x - gc.x, d1 = g4.y - gc.y, d2 = g4.z - gc.z;
        float kern = __expf(-0.5f*(d0*d0 + d1*d1 + d2*d2));
        const int xo = ((((ty+di)>>1)+1)*XP + (((tx+dj)>>1)+1)) * NC4;
        #pragma unroll
        for (int o = 0; o < CO; ++o) {
            float s = 0.f;
            #pragma unroll
            for (int c4 = 0; c4 < NC4; ++c4) {
                float4 xv = sx[xo + c4];
                float4 wv = swt[(k*CO + o)*NC4 + c4];
                s += wv.x*xv.x + wv.y*xv.y + wv.z*xv.z + wv.w*xv.w;
            }
            acc[o] += kern * s;
        }
    }
    const int h = h0 + ty, w = w0 + tx;
    #pragma unroll
    for (int o = 0; o < CO; ++o) {
        float v = acc[o];
        v = (v >= 0.f) ? v : 0.01f*v;
        out[(b*CO + o)*HW + h*W + w] = v;
    }
}

// ============================================================================
// pac_pair: CI=4 stages. Thread computes a 1x2 horizontal output pair.
// Tile 32x16 outputs, 256 threads (16 rows x 16 pairs).
// x window 2x3 float4 in registers; weights o-vectorized smem (CO=4) or
// regs (CO=1); guide halo smem with OOB sentinel. ACT: 1 leaky, 2 sigmoid.
// ============================================================================
#define PTW 32
#define PTH 16
#define PGP (PTW+2)            // 34
#define PGT ((PTH+2)*PGP)      // 612
#define PXP (PTW/2+2)          // 18
#define PXT ((PTH/2+2)*PXP)    // 180

template<int CO, int ACT>
__global__ __launch_bounds__(256) void pac_pair(
    const float* __restrict__ xin,   // (4,4,H/2,W/2)
    const float* __restrict__ gd,    // (4,3,H,W)
    const float* __restrict__ wt,    // (CO,4,3,3)
    float* __restrict__ out,         // (4,CO,H,W)
    int H, int W)
{
    __shared__ float4 sg[PGT];
    __shared__ float4 sx[PXT];
    __shared__ float4 swt[9*4];      // [k][ci] -> float4 over o (CO=4)

    const int tid = threadIdx.x;
    const int b   = blockIdx.z;
    const int h0  = blockIdx.y * PTH;
    const int w0  = blockIdx.x * PTW;
    const int HW  = H*W;
    const int H2 = H >> 1, W2 = W >> 1, HW2 = H2*W2;

    // ---- stage guide halo (sentinel OOB) ----
    const float* gb = gd + b*3*HW;
    for (int i = tid; i < PGT; i += 256) {
        int r = i / PGP, q = i - r*PGP;
        int gh = h0 - 1 + r, gw = w0 - 1 + q;
        float4 v;
        if ((gh >= 0) & (gh < H) & (gw >= 0) & (gw < W)) {
            int off = gh*W + gw;
            v.x = gb[off]; v.y = gb[HW + off]; v.z = gb[2*HW + off];
        } else { v.x = v.y = v.z = 1e19f; }
        v.w = 0.f;
        sg[i] = v;
    }
    // ---- stage x halo (half-res, zero pad) ----
    const float* xb = xin + b*4*HW2;
    for (int i = tid; i < PXT; i += 256) {
        int r = i / PXP, q = i - r*PXP;
        int xh = (h0>>1) - 1 + r, xw = (w0>>1) - 1 + q;
        float4 v = make_float4(0.f, 0.f, 0.f, 0.f);
        if ((xh >= 0) & (xh < H2) & (xw >= 0) & (xw < W2)) {
            int off = xh*W2 + xw;
            const float* p = xb + off;
            v.x = p[0]; v.y = p[HW2]; v.z = p[2*HW2]; v.w = p[3*HW2];
        }
        sx[i] = v;
    }
    // ---- weights ----
    float4 wr[CO == 1 ? 9 : 1];
    if (CO == 1) {
        #pragma unroll
        for (int k = 0; k < 9; ++k) {
            float4 v;
            v.x = __ldg(wt + 0*9 + k);
            v.y = __ldg(wt + 1*9 + k);
            v.z = __ldg(wt + 2*9 + k);
            v.w = __ldg(wt + 3*9 + k);
            wr[k] = v;
        }
    } else {
        if (tid < 36) {
            int ci = tid & 3, k = tid >> 2;
            float4 v;
            v.x = wt[(0*4 + ci)*9 + k];
            v.y = wt[(1*4 + ci)*9 + k];
            v.z = wt[(2*4 + ci)*9 + k];
            v.w = wt[(3*4 + ci)*9 + k];
            swt[k*4 + ci] = v;
        }
    }
    __syncthreads();

    const int ty = tid >> 4;          // 0..15 output row
    const int tx = tid & 15;          // pair index; pixel cols 2*tx, 2*tx+1

    // ---- x window 2x3 into registers ----
    // global x row for tap di: ((h+di)>>1); tile idx = ((ty+di)>>1)+1.
    // rows used: rb = ((ty-1)>>1)+1 and rb+1.  row for di=0: sel = 1-(ty&1).
    const int rb = ((ty-1)>>1) + 1;
    float4 xw[2][3];
    #pragma unroll
    for (int rr = 0; rr < 2; ++rr)
        #pragma unroll
        for (int cc = 0; cc < 3; ++cc)
            xw[rr][cc] = sx[(rb+rr)*PXP + (tx+cc)];
    const int midrow = 1 - (ty & 1);          // row index of di=0 taps
    float4 xmid[3];
    #pragma unroll
    for (int cc = 0; cc < 3; ++cc) xmid[cc] = xw[midrow][cc];

    // ---- guide centers ----
    const int gi0 = (ty+1)*PGP + (2*tx+1);
    const float4 gq0 = sg[gi0];
    const float4 gq1 = sg[gi0 + 1];

    float4 acc4[2];
    float  acc1[2];
    acc4[0] = make_float4(0.f,0.f,0.f,0.f);
    acc4[1] = make_float4(0.f,0.f,0.f,0.f);
    acc1[0] = acc1[1] = 0.f;

    #pragma unroll
    for (int k = 0; k < 9; ++k) {
        const int di = k/3 - 1, dj = k%3 - 1;
        // x-window selection (compile-time cols; row: di=-1 -> 0, di=1 -> 1, di=0 -> xmid)
        // col tile index for pixel c: ((2tx+c+dj)>>1)+1 -> local col sel = ((c+dj)>>1)+1
        float4 xv0, xv1;
        {
            const int cs0 = ((0+dj) >> 1) + 1;   // 0..1
            const int cs1 = ((1+dj) >> 1) + 1;   // 1..2
            if (di == -1)      { xv0 = xw[0][cs0]; xv1 = xw[0][cs1]; }
            else if (di == 1)  { xv0 = xw[1][cs0]; xv1 = xw[1][cs1]; }
            else               { xv0 = xmid[cs0];  xv1 = xmid[cs1];  }
        }
        float4 g0 = sg[gi0 + di*PGP + dj];
        float4 g1 = sg[gi0 + 1 + di*PGP + dj];
        float e0 = g0.x - gq0.x, e1 = g0.y - gq0.y, e2 = g0.z - gq0.z;
        float f0 = g1.x - gq1.x, f1 = g1.y - gq1.y, f2 = g1.z - gq1.z;
        float kern0 = __expf(-0.5f*(e0*e0 + e1*e1 + e2*e2));
        float kern1 = __expf(-0.5f*(f0*f0 + f1*f1 + f2*f2));

        if (CO == 4) {
            float4 wv0 = swt[k*4+0], wv1 = swt[k*4+1], wv2 = swt[k*4+2], wv3 = swt[k*4+3];
            acc4[0].x += kern0*(xv0.x*wv0.x + xv0.y*wv1.x + xv0.z*wv2.x + xv0.w*wv3.x);
            acc4[0].y += kern0*(xv0.x*wv0.y + xv0.y*wv1.y + xv0.z*wv2.y + xv0.w*wv3.y);
            acc4[0].z += kern0*(xv0.x*wv0.z + xv0.y*wv1.z + xv0.z*wv2.z + xv0.w*wv3.z);
            acc4[0].w += kern0*(xv0.x*wv0.w + xv0.y*wv1.w + xv0.z*wv2.w + xv0.w*wv3.w);
            acc4[1].x += kern1*(xv1.x*wv0.x + xv1.y*wv1.x + xv1.z*wv2.x + xv1.w*wv3.x);
            acc4[1].y += kern1*(xv1.x*wv0.y + xv1.y*wv1.y + xv1.z*wv2.y + xv1.w*wv3.y);
            acc4[1].z += kern1*(xv1.x*wv0.z + xv1.y*wv1.z + xv1.z*wv2.z + xv1.w*wv3.z);
            acc4[1].w += kern1*(xv1.x*wv0.w + xv1.y*wv1.w + xv1.z*wv2.w + xv1.w*wv3.w);
        } else {
            float4 wv = wr[k];
            acc1[0] += kern0*(xv0.x*wv.x + xv0.y*wv.y + xv0.z*wv.z + xv0.w*wv.w);
            acc1[1] += kern1*(xv1.x*wv.x + xv1.y*wv.y + xv1.z*wv.z + xv1.w*wv.w);
        }
    }

    const int h = h0 + ty, w = w0 + 2*tx;
    if (CO == 4) {
        float* op = out + b*4*HW + h*W + w;
        #pragma unroll
        for (int p = 0; p < 2; ++p) {
            acc4[p].x = (acc4[p].x >= 0.f) ? acc4[p].x : 0.01f*acc4[p].x;
            acc4[p].y = (acc4[p].y >= 0.f) ? acc4[p].y : 0.01f*acc4[p].y;
            acc4[p].z = (acc4[p].z >= 0.f) ? acc4[p].z : 0.01f*acc4[p].z;
            acc4[p].w = (acc4[p].w >= 0.f) ? acc4[p].w : 0.01f*acc4[p].w;
        }
        *(float2*)(op)        = make_float2(acc4[0].x, acc4[1].x);
        *(float2*)(op + HW)   = make_float2(acc4[0].y, acc4[1].y);
        *(float2*)(op + 2*HW) = make_float2(acc4[0].z, acc4[1].z);
        *(float2*)(op + 3*HW) = make_float2(acc4[0].w, acc4[1].w);
    } else {
        #pragma unroll
        for (int p = 0; p < 2; ++p) {
            if (ACT == 1) acc1[p] = (acc1[p] >= 0.f) ? acc1[p] : 0.01f*acc1[p];
            else          acc1[p] = 1.0f / (1.0f + __expf(-acc1[p]));
        }
        *(float2*)(out + b*HW + h*W + w) = make_float2(acc1[0], acc1[1]);
    }
}

// ---------------- launch ----------------
extern "C" void kernel_launch(void* const* d_in, const int* in_sizes, int n_in,
                              void* d_out, int out_size)
{
    const float* x     = (const float*)d_in[0];
    const float* guide = (const float*)d_in[1];
    const float* lin_w = (const float*)d_in[2];
    const float* lin_b = (const float*)d_in[3];
    const float* w0    = (const float*)d_in[4];
    const float* w1    = (const float*)d_in[5];
    const float* w2    = (const float*)d_in[6];
    const float* w3    = (const float*)d_in[7];
    float* out = (float*)d_out;

    float *x0, *xa, *xb, *xc, *gg64, *gg128, *gg256;
    cudaGetSymbolAddress((void**)&x0,    g_x0);
    cudaGetSymbolAddress((void**)&xa,    g_xa);
    cudaGetSymbolAddress((void**)&xb,    g_xb);
    cudaGetSymbolAddress((void**)&xc,    g_xc);
    cudaGetSymbolAddress((void**)&gg64,  g_g64);
    cudaGetSymbolAddress((void**)&gg128, g_g128);
    cudaGetSymbolAddress((void**)&gg256, g_g256);

    prep_kernel<<<1792, 256>>>(x, lin_w, lin_b, guide, x0, gg256, gg128, gg64);

    pac_tile<16,4><<<dim3( 2,  8, 4), 256>>>(x0, gg64,  w0, xa,  64,  64);
    pac_pair<4,1><<<dim3( 4,  8, 4), 256>>>(xa, gg128, w1, xb, 128, 128);
    pac_pair<4,1><<<dim3( 8, 16, 4), 256>>>(xb, gg256, w2, xc, 256, 256);
    pac_pair<1,2><<<dim3(16, 32, 4), 256>>>(xc, guide, w3, out, 512, 512);
}

// round 10
// speedup vs baseline: 1.1571x; 1.1571x over previous
#include <cuda_runtime.h>
#include <math.h>

// ---------------- scratch (__device__ globals; no allocations) ----------------
__device__ float g_x0 [4*16*32*32];
__device__ float g_xa [4*4*64*64];
__device__ float g_xb [4*4*128*128];
__device__ float g_xc [4*4*256*256];

#define GSTRIDE 262144            // 512*512 guide plane stride

// ============================================================================
// lin: 1x1 conv (384->16) + bias + leaky. 64 blocks x 256 threads.
// ============================================================================
__global__ __launch_bounds__(256) void lin_kernel(
    const float* __restrict__ x, const float* __restrict__ lw,
    const float* __restrict__ lb, float* __restrict__ x0)
{
    __shared__ float sw[16*384];
    const int tid = threadIdx.x;
    for (int i = tid; i < 16*384; i += 256) sw[i] = lw[i];
    __syncthreads();
    const int pix = blockIdx.x*64 + (tid & 63);
    const int b   = pix >> 10;
    const int hw  = pix & 1023;
    const int o0  = (tid >> 6) * 4;
    const float* xp  = x + b*384*1024 + hw;
    const float* w0p = sw + (o0+0)*384;
    const float* w1p = sw + (o0+1)*384;
    const float* w2p = sw + (o0+2)*384;
    const float* w3p = sw + (o0+3)*384;
    float a0=0.f, a1=0.f, a2=0.f, a3=0.f;
    #pragma unroll 4
    for (int i = 0; i < 384; ++i) {
        float xv = xp[i*1024];
        a0 += w0p[i]*xv; a1 += w1p[i]*xv; a2 += w2p[i]*xv; a3 += w3p[i]*xv;
    }
    a0 += lb[o0+0]; a1 += lb[o0+1]; a2 += lb[o0+2]; a3 += lb[o0+3];
    a0 = (a0 >= 0.f) ? a0 : 0.01f*a0;
    a1 = (a1 >= 0.f) ? a1 : 0.01f*a1;
    a2 = (a2 >= 0.f) ? a2 : 0.01f*a2;
    a3 = (a3 >= 0.f) ? a3 : 0.01f*a3;
    float* op = x0 + (b*16 + o0)*1024 + hw;
    op[0] = a0; op[1024] = a1; op[2048] = a2; op[3072] = a3;
}

// ---- fused guide fetch: level pixel (gh,gw) at factor F from 512x512 src ----
template<int F>
__device__ __forceinline__ float4 fetch_guide(const float* __restrict__ gb,
                                              int gh, int gw, int H, int W)
{
    float4 v;
    if ((gh >= 0) & (gh < H) & (gw >= 0) & (gw < W)) {
        if (F == 1) {
            int off = gh*512 + gw;
            v.x = gb[off];
            v.y = gb[off + GSTRIDE];
            v.z = gb[off + 2*GSTRIDE];
        } else {
            int off = (F*gh + (F>>1) - 1)*512 + (F*gw + (F>>1) - 1);
            v.x = 0.25f*(gb[off] + gb[off+1] + gb[off+512] + gb[off+513]);
            v.y = 0.25f*(gb[off+GSTRIDE] + gb[off+GSTRIDE+1] +
                         gb[off+GSTRIDE+512] + gb[off+GSTRIDE+513]);
            v.z = 0.25f*(gb[off+2*GSTRIDE] + gb[off+2*GSTRIDE+1] +
                         gb[off+2*GSTRIDE+512] + gb[off+2*GSTRIDE+513]);
        }
    } else {
        v.x = v.y = v.z = 1e19f;     // sentinel -> kern == 0 exactly
    }
    v.w = 0.f;
    return v;
}

// ============================================================================
// pac_tile: CI=16 stage (64x64 only), 256 threads, guide resize fused (F=8).
// ============================================================================
#define TW 32
#define TH 8
#define GP (TW+2)
#define GTILE ((TH+2)*GP)
#define XP (TW/2+2)
#define XTILE ((TH/2+2)*XP)

template<int CI, int CO, int F>
__global__ __launch_bounds__(256) void pac_tile(
    const float* __restrict__ xin, const float* __restrict__ guide,
    const float* __restrict__ wt, float* __restrict__ out,
    int H, int W)
{
    constexpr int NC4 = CI/4;
    __shared__ float4 sg[GTILE];
    __shared__ float4 sx[XTILE*NC4];
    __shared__ float4 swt[9*CO*NC4];

    const int tid = threadIdx.x;
    const int b   = blockIdx.z;
    const int h0  = blockIdx.y * TH;
    const int w0  = blockIdx.x * TW;
    const int HW  = H*W;
    const int H2 = H >> 1, W2 = W >> 1, HW2 = H2*W2;

    const float* gb = guide + b*3*GSTRIDE;
    for (int i = tid; i < GTILE; i += 256) {
        int r = i / GP, q = i - r*GP;
        sg[i] = fetch_guide<F>(gb, h0 - 1 + r, w0 - 1 + q, H, W);
    }
    const float* xb = xin + b*CI*HW2;
    for (int i = tid; i < XTILE*NC4; i += 256) {
        int pos = i / NC4, c4 = i - pos*NC4;
        int r = pos / XP, q = pos - r*XP;
        int xh = (h0>>1) - 1 + r, xw = (w0>>1) - 1 + q;
        float4 v = make_float4(0.f, 0.f, 0.f, 0.f);
        if ((xh >= 0) & (xh < H2) & (xw >= 0) & (xw < W2)) {
            int off = xh*W2 + xw;
            const float* p = xb + (c4*4)*HW2 + off;
            v.x = p[0]; v.y = p[HW2]; v.z = p[2*HW2]; v.w = p[3*HW2];
        }
        sx[i] = v;
    }
    for (int i = tid; i < 9*CO*NC4; i += 256) {
        int c4 = i % NC4;
        int t2 = i / NC4;
        int o  = t2 % CO;
        int k  = t2 / CO;
        float4 v;
        v.x = wt[(o*CI + c4*4 + 0)*9 + k];
        v.y = wt[(o*CI + c4*4 + 1)*9 + k];
        v.z = wt[(o*CI + c4*4 + 2)*9 + k];
        v.w = wt[(o*CI + c4*4 + 3)*9 + k];
        swt[i] = v;
    }
    __syncthreads();

    const int ty = tid >> 5, tx = tid & 31;
    const int gi0 = (ty+1)*GP + (tx+1);
    const float4 gc = sg[gi0];

    float acc[CO];
    #pragma unroll
    for (int o = 0; o < CO; ++o) acc[o] = 0.f;

    #pragma unroll
    for (int k = 0; k < 9; ++k) {
        const int di = k/3 - 1, dj = k%3 - 1;
        float4 g4 = sg[gi0 + di*GP + dj];
        float d0 = g4.x - gc.x, d1 = g4.y - gc.y, d2 = g4.z - gc.z;
        float kern = __expf(-0.5f*(d0*d0 + d1*d1 + d2*d2));
        const int xo = ((((ty+di)>>1)+1)*XP + (((tx+dj)>>1)+1)) * NC4;
        #pragma unroll
        for (int o = 0; o < CO; ++o) {
            float s = 0.f;
            #pragma unroll
            for (int c4 = 0; c4 < NC4; ++c4) {
                float4 xv = sx[xo + c4];
                float4 wv = swt[(k*CO + o)*NC4 + c4];
                s += wv.x*xv.x + wv.y*xv.y + wv.z*xv.z + wv.w*xv.w;
            }
            acc[o] += kern * s;
        }
    }
    const int h = h0 + ty, w = w0 + tx;
    #pragma unroll
    for (int o = 0; o < CO; ++o) {
        float v = acc[o];
        v = (v >= 0.f) ? v : 0.01f*v;
        out[(b*CO + o)*HW + h*W + w] = v;
    }
}

// ============================================================================
// pac_quad: CI=4 stages. 128 threads; thread computes a 2x2 output quad.
// Tile 32x16 outputs (16x8 quads). Guide resize fused via F.
// x window 3x3 float4 in regs; weights smem (CO=4) / regs (CO=1).
// ACT: 1 leaky, 2 sigmoid.
// ============================================================================
#define QTW 32
#define QTH 16
#define QGP (QTW+2)            // 34
#define QGH (QTH+2)            // 18
#define QGT (QGH*QGP)          // 612
#define QXP (QTW/2+2)          // 18
#define QXH (QTH/2+2)          // 10
#define QXT (QXH*QXP)          // 180

template<int CO, int ACT, int F>
__global__ __launch_bounds__(128) void pac_quad(
    const float* __restrict__ xin,    // (4,4,H/2,W/2)
    const float* __restrict__ guide,  // (4,3,512,512) original
    const float* __restrict__ wt,     // (CO,4,3,3)
    float* __restrict__ out,          // (4,CO,H,W)
    int H, int W)
{
    __shared__ float4 sg[QGT];
    __shared__ float4 sx[QXT];
    __shared__ float4 swt[9*4];

    const int tid = threadIdx.x;
    const int b   = blockIdx.z;
    const int h0  = blockIdx.y * QTH;
    const int w0  = blockIdx.x * QTW;
    const int HW  = H*W;
    const int H2 = H >> 1, W2 = W >> 1, HW2 = H2*W2;

    const float* gb = guide + b*3*GSTRIDE;
    for (int i = tid; i < QGT; i += 128) {
        int r = i / QGP, q = i - r*QGP;
        sg[i] = fetch_guide<F>(gb, h0 - 1 + r, w0 - 1 + q, H, W);
    }
    const float* xb = xin + b*4*HW2;
    for (int i = tid; i < QXT; i += 128) {
        int r = i / QXP, q = i - r*QXP;
        int xh = (h0>>1) - 1 + r, xw = (w0>>1) - 1 + q;
        float4 v = make_float4(0.f, 0.f, 0.f, 0.f);
        if ((xh >= 0) & (xh < H2) & (xw >= 0) & (xw < W2)) {
            int off = xh*W2 + xw;
            const float* p = xb + off;
            v.x = p[0]; v.y = p[HW2]; v.z = p[2*HW2]; v.w = p[3*HW2];
        }
        sx[i] = v;
    }
    float4 wr[CO == 1 ? 9 : 1];
    if (CO == 1) {
        #pragma unroll
        for (int k = 0; k < 9; ++k) {
            float4 v;
            v.x = __ldg(wt + 0*9 + k);
            v.y = __ldg(wt + 1*9 + k);
            v.z = __ldg(wt + 2*9 + k);
            v.w = __ldg(wt + 3*9 + k);
            wr[k] = v;
        }
    } else {
        if (tid < 36) {
            int ci = tid & 3, k = tid >> 2;
            float4 v;
            v.x = wt[(0*4 + ci)*9 + k];
            v.y = wt[(1*4 + ci)*9 + k];
            v.z = wt[(2*4 + ci)*9 + k];
            v.w = wt[(3*4 + ci)*9 + k];
            swt[k*4 + ci] = v;
        }
    }
    __syncthreads();

    const int qy = tid >> 4;        // 0..7
    const int qx = tid & 15;        // 0..15

    // ---- x window 3x3 float4 in registers ----
    float4 xw[9];
    #pragma unroll
    for (int rr = 0; rr < 3; ++rr)
        #pragma unroll
        for (int cc = 0; cc < 3; ++cc)
            xw[rr*3+cc] = sx[(qy+rr)*QXP + (qx+cc)];

    // ---- guide centers of the quad ----
    const int gbase = (2*qy+1)*QGP + (2*qx+1);
    float4 gq[4];
    gq[0] = sg[gbase];
    gq[1] = sg[gbase + 1];
    gq[2] = sg[gbase + QGP];
    gq[3] = sg[gbase + QGP + 1];

    float4 acc4[4];
    float  acc1[4];
    #pragma unroll
    for (int p = 0; p < 4; ++p) {
        acc4[p] = make_float4(0.f,0.f,0.f,0.f);
        acc1[p] = 0.f;
    }

    #pragma unroll
    for (int k = 0; k < 9; ++k) {
        const int di = k/3 - 1, dj = k%3 - 1;
        float4 wv0, wv1, wv2, wv3;
        if (CO == 4) {
            wv0 = swt[k*4+0]; wv1 = swt[k*4+1]; wv2 = swt[k*4+2]; wv3 = swt[k*4+3];
        }
        #pragma unroll
        for (int p = 0; p < 4; ++p) {
            const int rr = p >> 1, cc = p & 1;
            float4 g4 = sg[gbase + (rr+di)*QGP + (cc+dj)];
            float d0 = g4.x - gq[p].x, d1 = g4.y - gq[p].y, d2 = g4.z - gq[p].z;
            float kern = __expf(-0.5f*(d0*d0 + d1*d1 + d2*d2));
            const int xr = (rr + di + 2) >> 1;
            const int xc = (cc + dj + 2) >> 1;
            float4 xv = xw[xr*3 + xc];
            if (CO == 4) {
                acc4[p].x += kern*(xv.x*wv0.x + xv.y*wv1.x + xv.z*wv2.x + xv.w*wv3.x);
                acc4[p].y += kern*(xv.x*wv0.y + xv.y*wv1.y + xv.z*wv2.y + xv.w*wv3.y);
                acc4[p].z += kern*(xv.x*wv0.z + xv.y*wv1.z + xv.z*wv2.z + xv.w*wv3.z);
                acc4[p].w += kern*(xv.x*wv0.w + xv.y*wv1.w + xv.z*wv2.w + xv.w*wv3.w);
            } else {
                float4 wv = wr[k];
                acc1[p] += kern*(xv.x*wv.x + xv.y*wv.y + xv.z*wv.z + xv.w*wv.w);
            }
        }
    }

    const int h = h0 + 2*qy, w = w0 + 2*qx;
    if (CO == 4) {
        #pragma unroll
        for (int p = 0; p < 4; ++p) {
            float4 v = acc4[p];
            v.x = (v.x >= 0.f) ? v.x : 0.01f*v.x;
            v.y = (v.y >= 0.f) ? v.y : 0.01f*v.y;
            v.z = (v.z >= 0.f) ? v.z : 0.01f*v.z;
            v.w = (v.w >= 0.f) ? v.w : 0.01f*v.w;
            acc4[p] = v;
        }
        float* op = out + b*4*HW + h*W + w;
        *(float2*)(op)            = make_float2(acc4[0].x, acc4[1].x);
        *(float2*)(op + W)        = make_float2(acc4[2].x, acc4[3].x);
        op += HW;
        *(float2*)(op)            = make_float2(acc4[0].y, acc4[1].y);
        *(float2*)(op + W)        = make_float2(acc4[2].y, acc4[3].y);
        op += HW;
        *(float2*)(op)            = make_float2(acc4[0].z, acc4[1].z);
        *(float2*)(op + W)        = make_float2(acc4[2].z, acc4[3].z);
        op += HW;
        *(float2*)(op)            = make_float2(acc4[0].w, acc4[1].w);
        *(float2*)(op + W)        = make_float2(acc4[2].w, acc4[3].w);
    } else {
        #pragma unroll
        for (int p = 0; p < 4; ++p) {
            if (ACT == 1) acc1[p] = (acc1[p] >= 0.f) ? acc1[p] : 0.01f*acc1[p];
            else          acc1[p] = 1.0f / (1.0f + __expf(-acc1[p]));
        }
        float* op = out + b*HW + h*W + w;
        *(float2*)(op)     = make_float2(acc1[0], acc1[1]);
        *(float2*)(op + W) = make_float2(acc1[2], acc1[3]);
    }
}

// ---------------- launch ----------------
extern "C" void kernel_launch(void* const* d_in, const int* in_sizes, int n_in,
                              void* d_out, int out_size)
{
    const float* x     = (const float*)d_in[0];
    const float* guide = (const float*)d_in[1];
    const float* lin_w = (const float*)d_in[2];
    const float* lin_b = (const float*)d_in[3];
    const float* w0    = (const float*)d_in[4];
    const float* w1    = (const float*)d_in[5];
    const float* w2    = (const float*)d_in[6];
    const float* w3    = (const float*)d_in[7];
    float* out = (float*)d_out;

    float *x0, *xa, *xb, *xc;
    cudaGetSymbolAddress((void**)&x0, g_x0);
    cudaGetSymbolAddress((void**)&xa, g_xa);
    cudaGetSymbolAddress((void**)&xb, g_xb);
    cudaGetSymbolAddress((void**)&xc, g_xc);

    lin_kernel<<<64, 256>>>(x, lin_w, lin_b, x0);

    pac_tile<16,4,8><<<dim3( 2,  8, 4), 256>>>(x0, guide, w0, xa,  64,  64);
    pac_quad<4,1,4><<<dim3( 4,  8, 4), 128>>>(xa, guide, w1, xb, 128, 128);
    pac_quad<4,1,2><<<dim3( 8, 16, 4), 128>>>(xb, guide, w2, xc, 256, 256);
    pac_quad<1,2,1><<<dim3(16, 32, 4), 128>>>(xc, guide, w3, out, 512, 512);
}

// round 11
// speedup vs baseline: 1.1578x; 1.0006x over previous
#include <cuda_runtime.h>
#include <math.h>

// ---------------- scratch (__device__ globals; no allocations) ----------------
__device__ float g_x0 [4*16*32*32];
__device__ float g_xa [4*4*64*64];
__device__ float g_xb [4*4*128*128];
__device__ float g_xc [4*4*256*256];

#define GSTRIDE 262144            // 512*512 guide plane stride

// ============================================================================
// lin: 1x1 conv (384->16) + bias + leaky. 64 blocks x 256 threads.
// ============================================================================
__global__ __launch_bounds__(256) void lin_kernel(
    const float* __restrict__ x, const float* __restrict__ lw,
    const float* __restrict__ lb, float* __restrict__ x0)
{
    __shared__ float sw[16*384];
    const int tid = threadIdx.x;
    for (int i = tid; i < 16*384; i += 256) sw[i] = lw[i];
    __syncthreads();
    const int pix = blockIdx.x*64 + (tid & 63);
    const int b   = pix >> 10;
    const int hw  = pix & 1023;
    const int o0  = (tid >> 6) * 4;
    const float* xp  = x + b*384*1024 + hw;
    const float* w0p = sw + (o0+0)*384;
    const float* w1p = sw + (o0+1)*384;
    const float* w2p = sw + (o0+2)*384;
    const float* w3p = sw + (o0+3)*384;
    float a0=0.f, a1=0.f, a2=0.f, a3=0.f;
    #pragma unroll 4
    for (int i = 0; i < 384; ++i) {
        float xv = xp[i*1024];
        a0 += w0p[i]*xv; a1 += w1p[i]*xv; a2 += w2p[i]*xv; a3 += w3p[i]*xv;
    }
    a0 += lb[o0+0]; a1 += lb[o0+1]; a2 += lb[o0+2]; a3 += lb[o0+3];
    a0 = (a0 >= 0.f) ? a0 : 0.01f*a0;
    a1 = (a1 >= 0.f) ? a1 : 0.01f*a1;
    a2 = (a2 >= 0.f) ? a2 : 0.01f*a2;
    a3 = (a3 >= 0.f) ? a3 : 0.01f*a3;
    float* op = x0 + (b*16 + o0)*1024 + hw;
    op[0] = a0; op[1024] = a1; op[2048] = a2; op[3072] = a3;
}

// ---- fused guide fetch: level pixel (gh,gw) at factor F from 512x512 src ----
template<int F>
__device__ __forceinline__ float4 fetch_guide(const float* __restrict__ gb,
                                              int gh, int gw, int H, int W)
{
    float4 v;
    if ((gh >= 0) & (gh < H) & (gw >= 0) & (gw < W)) {
        if (F == 1) {
            int off = gh*512 + gw;
            v.x = gb[off];
            v.y = gb[off + GSTRIDE];
            v.z = gb[off + 2*GSTRIDE];
        } else if (F == 2) {
            // box at rows 2gh..2gh+1, cols 2gw..2gw+1 (even col -> aligned float2)
            int off = (2*gh)*512 + 2*gw;
            float2 a0 = *(const float2*)(gb + off);
            float2 a1 = *(const float2*)(gb + off + 512);
            float2 b0 = *(const float2*)(gb + off + GSTRIDE);
            float2 b1 = *(const float2*)(gb + off + GSTRIDE + 512);
            float2 c0 = *(const float2*)(gb + off + 2*GSTRIDE);
            float2 c1 = *(const float2*)(gb + off + 2*GSTRIDE + 512);
            v.x = 0.25f*(a0.x + a0.y + a1.x + a1.y);
            v.y = 0.25f*(b0.x + b0.y + b1.x + b1.y);
            v.z = 0.25f*(c0.x + c0.y + c1.x + c1.y);
        } else if (F == 4) {
            // box at rows 4gh+1..2, cols 4gw+1..2 -> inside aligned float4 at col 4gw
            int off = (4*gh + 1)*512 + 4*gw;
            float4 a0 = *(const float4*)(gb + off);
            float4 a1 = *(const float4*)(gb + off + 512);
            float4 b0 = *(const float4*)(gb + off + GSTRIDE);
            float4 b1 = *(const float4*)(gb + off + GSTRIDE + 512);
            float4 c0 = *(const float4*)(gb + off + 2*GSTRIDE);
            float4 c1 = *(const float4*)(gb + off + 2*GSTRIDE + 512);
            v.x = 0.25f*(a0.y + a0.z + a1.y + a1.z);
            v.y = 0.25f*(b0.y + b0.z + b1.y + b1.z);
            v.z = 0.25f*(c0.y + c0.z + c1.y + c1.z);
        } else {
            int off = (F*gh + (F>>1) - 1)*512 + (F*gw + (F>>1) - 1);
            v.x = 0.25f*(gb[off] + gb[off+1] + gb[off+512] + gb[off+513]);
            v.y = 0.25f*(gb[off+GSTRIDE] + gb[off+GSTRIDE+1] +
                         gb[off+GSTRIDE+512] + gb[off+GSTRIDE+513]);
            v.z = 0.25f*(gb[off+2*GSTRIDE] + gb[off+2*GSTRIDE+1] +
                         gb[off+2*GSTRIDE+512] + gb[off+2*GSTRIDE+513]);
        }
    } else {
        v.x = v.y = v.z = 1e19f;     // sentinel -> kern == 0 exactly
    }
    v.w = 0.f;
    return v;
}

// ============================================================================
// pac_tile: CI=16 stage (64x64 only), 256 threads, guide resize fused (F=8).
// ============================================================================
#define TW 32
#define TH 8
#define GP (TW+2)
#define GTILE ((TH+2)*GP)
#define XP (TW/2+2)
#define XTILE ((TH/2+2)*XP)

template<int CI, int CO, int F>
__global__ __launch_bounds__(256) void pac_tile(
    const float* __restrict__ xin, const float* __restrict__ guide,
    const float* __restrict__ wt, float* __restrict__ out,
    int H, int W)
{
    constexpr int NC4 = CI/4;
    __shared__ float4 sg[GTILE];
    __shared__ float4 sx[XTILE*NC4];
    __shared__ float4 swt[9*CO*NC4];

    const int tid = threadIdx.x;
    const int b   = blockIdx.z;
    const int h0  = blockIdx.y * TH;
    const int w0  = blockIdx.x * TW;
    const int HW  = H*W;
    const int H2 = H >> 1, W2 = W >> 1, HW2 = H2*W2;

    const float* gb = guide + b*3*GSTRIDE;
    for (int i = tid; i < GTILE; i += 256) {
        int r = i / GP, q = i - r*GP;
        sg[i] = fetch_guide<F>(gb, h0 - 1 + r, w0 - 1 + q, H, W);
    }
    const float* xb = xin + b*CI*HW2;
    for (int i = tid; i < XTILE*NC4; i += 256) {
        int pos = i / NC4, c4 = i - pos*NC4;
        int r = pos / XP, q = pos - r*XP;
        int xh = (h0>>1) - 1 + r, xw = (w0>>1) - 1 + q;
        float4 v = make_float4(0.f, 0.f, 0.f, 0.f);
        if ((xh >= 0) & (xh < H2) & (xw >= 0) & (xw < W2)) {
            int off = xh*W2 + xw;
            const float* p = xb + (c4*4)*HW2 + off;
            v.x = p[0]; v.y = p[HW2]; v.z = p[2*HW2]; v.w = p[3*HW2];
        }
        sx[i] = v;
    }
    for (int i = tid; i < 9*CO*NC4; i += 256) {
        int c4 = i % NC4;
        int t2 = i / NC4;
        int o  = t2 % CO;
        int k  = t2 / CO;
        float4 v;
        v.x = wt[(o*CI + c4*4 + 0)*9 + k];
        v.y = wt[(o*CI + c4*4 + 1)*9 + k];
        v.z = wt[(o*CI + c4*4 + 2)*9 + k];
        v.w = wt[(o*CI + c4*4 + 3)*9 + k];
        swt[i] = v;
    }
    __syncthreads();

    const int ty = tid >> 5, tx = tid & 31;
    const int gi0 = (ty+1)*GP + (tx+1);
    const float4 gc = sg[gi0];

    float acc[CO];
    #pragma unroll
    for (int o = 0; o < CO; ++o) acc[o] = 0.f;

    #pragma unroll
    for (int k = 0; k < 9; ++k) {
        const int di = k/3 - 1, dj = k%3 - 1;
        float4 g4 = sg[gi0 + di*GP + dj];
        float d0 = g4.x - gc.x, d1 = g4.y - gc.y, d2 = g4.z - gc.z;
        float kern = __expf(-0.5f*(d0*d0 + d1*d1 + d2*d2));
        const int xo = ((((ty+di)>>1)+1)*XP + (((tx+dj)>>1)+1)) * NC4;
        #pragma unroll
        for (int o = 0; o < CO; ++o) {
            float s = 0.f;
            #pragma unroll
            for (int c4 = 0; c4 < NC4; ++c4) {
                float4 xv = sx[xo + c4];
                float4 wv = swt[(k*CO + o)*NC4 + c4];
                s += wv.x*xv.x + wv.y*xv.y + wv.z*xv.z + wv.w*xv.w;
            }
            acc[o] += kern * s;
        }
    }
    const int h = h0 + ty, w = w0 + tx;
    #pragma unroll
    for (int o = 0; o < CO; ++o) {
        float v = acc[o];
        v = (v >= 0.f) ? v : 0.01f*v;
        out[(b*CO + o)*HW + h*W + w] = v;
    }
}

// ============================================================================
// pac_pair: CI=4 mid stages (128^2, 256^2). 256 threads; thread computes a
// 1x2 horizontal pair. Tile 32x16. Guide resize fused via F.
// ============================================================================
#define PTW 32
#define PTH 16
#define PGP (PTW+2)            // 34
#define PGT ((PTH+2)*PGP)      // 612
#define PXP (PTW/2+2)          // 18
#define PXT ((PTH/2+2)*PXP)    // 180

template<int CO, int ACT, int F>
__global__ __launch_bounds__(256) void pac_pair(
    const float* __restrict__ xin,    // (4,4,H/2,W/2)
    const float* __restrict__ guide,  // (4,3,512,512)
    const float* __restrict__ wt,     // (CO,4,3,3)
    float* __restrict__ out,          // (4,CO,H,W)
    int H, int W)
{
    __shared__ float4 sg[PGT];
    __shared__ float4 sx[PXT];
    __shared__ float4 swt[9*4];

    const int tid = threadIdx.x;
    const int b   = blockIdx.z;
    const int h0  = blockIdx.y * PTH;
    const int w0  = blockIdx.x * PTW;
    const int HW  = H*W;
    const int H2 = H >> 1, W2 = W >> 1, HW2 = H2*W2;

    const float* gb = guide + b*3*GSTRIDE;
    for (int i = tid; i < PGT; i += 256) {
        int r = i / PGP, q = i - r*PGP;
        sg[i] = fetch_guide<F>(gb, h0 - 1 + r, w0 - 1 + q, H, W);
    }
    const float* xb = xin + b*4*HW2;
    for (int i = tid; i < PXT; i += 256) {
        int r = i / PXP, q = i - r*PXP;
        int xh = (h0>>1) - 1 + r, xw = (w0>>1) - 1 + q;
        float4 v = make_float4(0.f, 0.f, 0.f, 0.f);
        if ((xh >= 0) & (xh < H2) & (xw >= 0) & (xw < W2)) {
            int off = xh*W2 + xw;
            const float* p = xb + off;
            v.x = p[0]; v.y = p[HW2]; v.z = p[2*HW2]; v.w = p[3*HW2];
        }
        sx[i] = v;
    }
    if (tid < 36) {
        int ci = tid & 3, k = tid >> 2;
        float4 v;
        v.x = wt[(0*4 + ci)*9 + k];
        v.y = wt[(1*4 + ci)*9 + k];
        v.z = wt[(2*4 + ci)*9 + k];
        v.w = wt[(3*4 + ci)*9 + k];
        swt[k*4 + ci] = v;
    }
    __syncthreads();

    const int ty = tid >> 4;          // 0..15 output row
    const int tx = tid & 15;          // pair index; pixel cols 2*tx, 2*tx+1

    const int rb = ((ty-1)>>1) + 1;
    float4 xw[2][3];
    #pragma unroll
    for (int rr = 0; rr < 2; ++rr)
        #pragma unroll
        for (int cc = 0; cc < 3; ++cc)
            xw[rr][cc] = sx[(rb+rr)*PXP + (tx+cc)];
    const int midrow = 1 - (ty & 1);
    float4 xmid[3];
    #pragma unroll
    for (int cc = 0; cc < 3; ++cc) xmid[cc] = xw[midrow][cc];

    const int gi0 = (ty+1)*PGP + (2*tx+1);
    const float4 gq0 = sg[gi0];
    const float4 gq1 = sg[gi0 + 1];

    float4 acc4[2];
    acc4[0] = make_float4(0.f,0.f,0.f,0.f);
    acc4[1] = make_float4(0.f,0.f,0.f,0.f);

    #pragma unroll
    for (int k = 0; k < 9; ++k) {
        const int di = k/3 - 1, dj = k%3 - 1;
        float4 xv0, xv1;
        {
            const int cs0 = ((0+dj) >> 1) + 1;
            const int cs1 = ((1+dj) >> 1) + 1;
            if (di == -1)      { xv0 = xw[0][cs0]; xv1 = xw[0][cs1]; }
            else if (di == 1)  { xv0 = xw[1][cs0]; xv1 = xw[1][cs1]; }
            else               { xv0 = xmid[cs0];  xv1 = xmid[cs1];  }
        }
        float4 g0 = sg[gi0 + di*PGP + dj];
        float4 g1 = sg[gi0 + 1 + di*PGP + dj];
        float e0 = g0.x - gq0.x, e1 = g0.y - gq0.y, e2 = g0.z - gq0.z;
        float f0 = g1.x - gq1.x, f1 = g1.y - gq1.y, f2 = g1.z - gq1.z;
        float kern0 = __expf(-0.5f*(e0*e0 + e1*e1 + e2*e2));
        float kern1 = __expf(-0.5f*(f0*f0 + f1*f1 + f2*f2));

        float4 wv0 = swt[k*4+0], wv1 = swt[k*4+1], wv2 = swt[k*4+2], wv3 = swt[k*4+3];
        acc4[0].x += kern0*(xv0.x*wv0.x + xv0.y*wv1.x + xv0.z*wv2.x + xv0.w*wv3.x);
        acc4[0].y += kern0*(xv0.x*wv0.y + xv0.y*wv1.y + xv0.z*wv2.y + xv0.w*wv3.y);
        acc4[0].z += kern0*(xv0.x*wv0.z + xv0.y*wv1.z + xv0.z*wv2.z + xv0.w*wv3.z);
        acc4[0].w += kern0*(xv0.x*wv0.w + xv0.y*wv1.w + xv0.z*wv2.w + xv0.w*wv3.w);
        acc4[1].x += kern1*(xv1.x*wv0.x + xv1.y*wv1.x + xv1.z*wv2.x + xv1.w*wv3.x);
        acc4[1].y += kern1*(xv1.x*wv0.y + xv1.y*wv1.y + xv1.z*wv2.y + xv1.w*wv3.y);
        acc4[1].z += kern1*(xv1.x*wv0.z + xv1.y*wv1.z + xv1.z*wv2.z + xv1.w*wv3.z);
        acc4[1].w += kern1*(xv1.x*wv0.w + xv1.y*wv1.w + xv1.z*wv2.w + xv1.w*wv3.w);
    }

    const int h = h0 + ty, w = w0 + 2*tx;
    float* op = out + b*4*HW + h*W + w;
    #pragma unroll
    for (int p = 0; p < 2; ++p) {
        acc4[p].x = (acc4[p].x >= 0.f) ? acc4[p].x : 0.01f*acc4[p].x;
        acc4[p].y = (acc4[p].y >= 0.f) ? acc4[p].y : 0.01f*acc4[p].y;
        acc4[p].z = (acc4[p].z >= 0.f) ? acc4[p].z : 0.01f*acc4[p].z;
        acc4[p].w = (acc4[p].w >= 0.f) ? acc4[p].w : 0.01f*acc4[p].w;
    }
    *(float2*)(op)        = make_float2(acc4[0].x, acc4[1].x);
    *(float2*)(op + HW)   = make_float2(acc4[0].y, acc4[1].y);
    *(float2*)(op + 2*HW) = make_float2(acc4[0].z, acc4[1].z);
    *(float2*)(op + 3*HW) = make_float2(acc4[0].w, acc4[1].w);
}

// ============================================================================
// pac_quad: 512^2 final stage (CO=1, sigmoid). 128 threads; 2x2 quads.
// ============================================================================
#define QTW 32
#define QTH 16
#define QGP (QTW+2)
#define QGT ((QTH+2)*QGP)
#define QXP (QTW/2+2)
#define QXT ((QTH/2+2)*QXP)

template<int CO, int ACT, int F>
__global__ __launch_bounds__(128) void pac_quad(
    const float* __restrict__ xin,
    const float* __restrict__ guide,
    const float* __restrict__ wt,
    float* __restrict__ out,
    int H, int W)
{
    __shared__ float4 sg[QGT];
    __shared__ float4 sx[QXT];

    const int tid = threadIdx.x;
    const int b   = blockIdx.z;
    const int h0  = blockIdx.y * QTH;
    const int w0  = blockIdx.x * QTW;
    const int HW  = H*W;
    const int H2 = H >> 1, W2 = W >> 1, HW2 = H2*W2;

    const float* gb = guide + b*3*GSTRIDE;
    for (int i = tid; i < QGT; i += 128) {
        int r = i / QGP, q = i - r*QGP;
        sg[i] = fetch_guide<F>(gb, h0 - 1 + r, w0 - 1 + q, H, W);
    }
    const float* xb = xin + b*4*HW2;
    for (int i = tid; i < QXT; i += 128) {
        int r = i / QXP, q = i - r*QXP;
        int xh = (h0>>1) - 1 + r, xw = (w0>>1) - 1 + q;
        float4 v = make_float4(0.f, 0.f, 0.f, 0.f);
        if ((xh >= 0) & (xh < H2) & (xw >= 0) & (xw < W2)) {
            int off = xh*W2 + xw;
            const float* p = xb + off;
            v.x = p[0]; v.y = p[HW2]; v.z = p[2*HW2]; v.w = p[3*HW2];
        }
        sx[i] = v;
    }
    float4 wr[9];
    #pragma unroll
    for (int k = 0; k < 9; ++k) {
        float4 v;
        v.x = __ldg(wt + 0*9 + k);
        v.y = __ldg(wt + 1*9 + k);
        v.z = __ldg(wt + 2*9 + k);
        v.w = __ldg(wt + 3*9 + k);
        wr[k] = v;
    }
    __syncthreads();

    const int qy = tid >> 4;
    const int qx = tid & 15;

    float4 xw[9];
    #pragma unroll
    for (int rr = 0; rr < 3; ++rr)
        #pragma unroll
        for (int cc = 0; cc < 3; ++cc)
            xw[rr*3+cc] = sx[(qy+rr)*QXP + (qx+cc)];

    const int gbase = (2*qy+1)*QGP + (2*qx+1);
    float4 gq[4];
    gq[0] = sg[gbase];
    gq[1] = sg[gbase + 1];
    gq[2] = sg[gbase + QGP];
    gq[3] = sg[gbase + QGP + 1];

    float acc1[4] = {0.f, 0.f, 0.f, 0.f};

    #pragma unroll
    for (int k = 0; k < 9; ++k) {
        const int di = k/3 - 1, dj = k%3 - 1;
        #pragma unroll
        for (int p = 0; p < 4; ++p) {
            const int rr = p >> 1, cc = p & 1;
            float4 g4 = sg[gbase + (rr+di)*QGP + (cc+dj)];
            float d0 = g4.x - gq[p].x, d1 = g4.y - gq[p].y, d2 = g4.z - gq[p].z;
            float kern = __expf(-0.5f*(d0*d0 + d1*d1 + d2*d2));
            const int xr = (rr + di + 2) >> 1;
            const int xc = (cc + dj + 2) >> 1;
            float4 xv = xw[xr*3 + xc];
            float4 wv = wr[k];
            acc1[p] += kern*(xv.x*wv.x + xv.y*wv.y + xv.z*wv.z + xv.w*wv.w);
        }
    }

    const int h = h0 + 2*qy, w = w0 + 2*qx;
    #pragma unroll
    for (int p = 0; p < 4; ++p) {
        if (ACT == 1) acc1[p] = (acc1[p] >= 0.f) ? acc1[p] : 0.01f*acc1[p];
        else          acc1[p] = 1.0f / (1.0f + __expf(-acc1[p]));
    }
    float* op = out + b*HW + h*W + w;
    *(float2*)(op)     = make_float2(acc1[0], acc1[1]);
    *(float2*)(op + W) = make_float2(acc1[2], acc1[3]);
}

// ---------------- launch ----------------
extern "C" void kernel_launch(void* const* d_in, const int* in_sizes, int n_in,
                              void* d_out, int out_size)
{
    const float* x     = (const float*)d_in[0];
    const float* guide = (const float*)d_in[1];
    const float* lin_w = (const float*)d_in[2];
    const float* lin_b = (const float*)d_in[3];
    const float* w0    = (const float*)d_in[4];
    const float* w1    = (const float*)d_in[5];
    const float* w2    = (const float*)d_in[6];
    const float* w3    = (const float*)d_in[7];
    float* out = (float*)d_out;

    float *x0, *xa, *xb, *xc;
    cudaGetSymbolAddress((void**)&x0, g_x0);
    cudaGetSymbolAddress((void**)&xa, g_xa);
    cudaGetSymbolAddress((void**)&xb, g_xb);
    cudaGetSymbolAddress((void**)&xc, g_xc);

    lin_kernel<<<64, 256>>>(x, lin_w, lin_b, x0);

    pac_tile<16,4,8><<<dim3( 2,  8, 4), 256>>>(x0, guide, w0, xa,  64,  64);
    pac_pair<4,1,4><<<dim3( 4,  8, 4), 256>>>(xa, guide, w1, xb, 128, 128);
    pac_pair<4,1,2><<<dim3( 8, 16, 4), 256>>>(xb, guide, w2, xc, 256, 256);
    pac_quad<1,2,1><<<dim3(16, 32, 4), 128>>>(xc, guide, w3, out, 512, 512);
}

// round 12
// speedup vs baseline: 1.1962x; 1.0332x over previous
#include <cuda_runtime.h>
#include <math.h>

// ---------------- scratch (__device__ globals; no allocations) ----------------
__device__ float g_x0 [4*16*32*32];
__device__ float g_xa [4*4*64*64];
__device__ float g_xb [4*4*128*128];
__device__ float g_xc [4*4*256*256];

#define GSTRIDE 262144            // 512*512 guide plane stride

// ============================================================================
// lin: 1x1 conv (384->16) + bias + leaky. 64 blocks x 256 threads.
// ============================================================================
__global__ __launch_bounds__(256) void lin_kernel(
    const float* __restrict__ x, const float* __restrict__ lw,
    const float* __restrict__ lb, float* __restrict__ x0)
{
    __shared__ float sw[16*384];
    const int tid = threadIdx.x;
    for (int i = tid; i < 16*384; i += 256) sw[i] = lw[i];
    __syncthreads();
    const int pix = blockIdx.x*64 + (tid & 63);
    const int b   = pix >> 10;
    const int hw  = pix & 1023;
    const int o0  = (tid >> 6) * 4;
    const float* xp  = x + b*384*1024 + hw;
    const float* w0p = sw + (o0+0)*384;
    const float* w1p = sw + (o0+1)*384;
    const float* w2p = sw + (o0+2)*384;
    const float* w3p = sw + (o0+3)*384;
    float a0=0.f, a1=0.f, a2=0.f, a3=0.f;
    #pragma unroll 4
    for (int i = 0; i < 384; ++i) {
        float xv = xp[i*1024];
        a0 += w0p[i]*xv; a1 += w1p[i]*xv; a2 += w2p[i]*xv; a3 += w3p[i]*xv;
    }
    a0 += lb[o0+0]; a1 += lb[o0+1]; a2 += lb[o0+2]; a3 += lb[o0+3];
    a0 = (a0 >= 0.f) ? a0 : 0.01f*a0;
    a1 = (a1 >= 0.f) ? a1 : 0.01f*a1;
    a2 = (a2 >= 0.f) ? a2 : 0.01f*a2;
    a3 = (a3 >= 0.f) ? a3 : 0.01f*a3;
    float* op = x0 + (b*16 + o0)*1024 + hw;
    op[0] = a0; op[1024] = a1; op[2048] = a2; op[3072] = a3;
}

// ---- fused guide fetch: level pixel (gh,gw) at factor F from 512x512 src ----
template<int F>
__device__ __forceinline__ float4 fetch_guide(const float* __restrict__ gb,
                                              int gh, int gw, int H, int W)
{
    float4 v;
    if ((gh >= 0) & (gh < H) & (gw >= 0) & (gw < W)) {
        if (F == 1) {
            int off = gh*512 + gw;
            v.x = gb[off];
            v.y = gb[off + GSTRIDE];
            v.z = gb[off + 2*GSTRIDE];
        } else if (F == 2) {
            int off = (2*gh)*512 + 2*gw;
            float2 a0 = *(const float2*)(gb + off);
            float2 a1 = *(const float2*)(gb + off + 512);
            float2 b0 = *(const float2*)(gb + off + GSTRIDE);
            float2 b1 = *(const float2*)(gb + off + GSTRIDE + 512);
            float2 c0 = *(const float2*)(gb + off + 2*GSTRIDE);
            float2 c1 = *(const float2*)(gb + off + 2*GSTRIDE + 512);
            v.x = 0.25f*(a0.x + a0.y + a1.x + a1.y);
            v.y = 0.25f*(b0.x + b0.y + b1.x + b1.y);
            v.z = 0.25f*(c0.x + c0.y + c1.x + c1.y);
        } else if (F == 4) {
            int off = (4*gh + 1)*512 + 4*gw;
            float4 a0 = *(const float4*)(gb + off);
            float4 a1 = *(const float4*)(gb + off + 512);
            float4 b0 = *(const float4*)(gb + off + GSTRIDE);
            float4 b1 = *(const float4*)(gb + off + GSTRIDE + 512);
            float4 c0 = *(const float4*)(gb + off + 2*GSTRIDE);
            float4 c1 = *(const float4*)(gb + off + 2*GSTRIDE + 512);
            v.x = 0.25f*(a0.y + a0.z + a1.y + a1.z);
            v.y = 0.25f*(b0.y + b0.z + b1.y + b1.z);
            v.z = 0.25f*(c0.y + c0.z + c1.y + c1.z);
        } else {
            int off = (F*gh + (F>>1) - 1)*512 + (F*gw + (F>>1) - 1);
            v.x = 0.25f*(gb[off] + gb[off+1] + gb[off+512] + gb[off+513]);
            v.y = 0.25f*(gb[off+GSTRIDE] + gb[off+GSTRIDE+1] +
                         gb[off+GSTRIDE+512] + gb[off+GSTRIDE+513]);
            v.z = 0.25f*(gb[off+2*GSTRIDE] + gb[off+2*GSTRIDE+1] +
                         gb[off+2*GSTRIDE+512] + gb[off+2*GSTRIDE+513]);
        }
    } else {
        v.x = v.y = v.z = 1e19f;     // sentinel -> kern == 0 exactly
    }
    v.w = 0.f;
    return v;
}

// ============================================================================
// pac_tile: CI=16 stage (64x64 only), 256 threads, guide resize fused (F=8).
// ============================================================================
#define TW 32
#define TH 8
#define GP (TW+2)
#define GTILE ((TH+2)*GP)
#define XP (TW/2+2)
#define XTILE ((TH/2+2)*XP)

template<int CI, int CO, int F>
__global__ __launch_bounds__(256) void pac_tile(
    const float* __restrict__ xin, const float* __restrict__ guide,
    const float* __restrict__ wt, float* __restrict__ out,
    int H, int W)
{
    constexpr int NC4 = CI/4;
    __shared__ float4 sg[GTILE];
    __shared__ float4 sx[XTILE*NC4];
    __shared__ float4 swt[9*CO*NC4];

    const int tid = threadIdx.x;
    const int b   = blockIdx.z;
    const int h0  = blockIdx.y * TH;
    const int w0  = blockIdx.x * TW;
    const int HW  = H*W;
    const int H2 = H >> 1, W2 = W >> 1, HW2 = H2*W2;

    const float* gb = guide + b*3*GSTRIDE;
    for (int i = tid; i < GTILE; i += 256) {
        int r = i / GP, q = i - r*GP;
        sg[i] = fetch_guide<F>(gb, h0 - 1 + r, w0 - 1 + q, H, W);
    }
    const float* xb = xin + b*CI*HW2;
    for (int i = tid; i < XTILE*NC4; i += 256) {
        int pos = i / NC4, c4 = i - pos*NC4;
        int r = pos / XP, q = pos - r*XP;
        int xh = (h0>>1) - 1 + r, xw = (w0>>1) - 1 + q;
        float4 v = make_float4(0.f, 0.f, 0.f, 0.f);
        if ((xh >= 0) & (xh < H2) & (xw >= 0) & (xw < W2)) {
            int off = xh*W2 + xw;
            const float* p = xb + (c4*4)*HW2 + off;
            v.x = p[0]; v.y = p[HW2]; v.z = p[2*HW2]; v.w = p[3*HW2];
        }
        sx[i] = v;
    }
    for (int i = tid; i < 9*CO*NC4; i += 256) {
        int c4 = i % NC4;
        int t2 = i / NC4;
        int o  = t2 % CO;
        int k  = t2 / CO;
        float4 v;
        v.x = wt[(o*CI + c4*4 + 0)*9 + k];
        v.y = wt[(o*CI + c4*4 + 1)*9 + k];
        v.z = wt[(o*CI + c4*4 + 2)*9 + k];
        v.w = wt[(o*CI + c4*4 + 3)*9 + k];
        swt[i] = v;
    }
    __syncthreads();

    const int ty = tid >> 5, tx = tid & 31;
    const int gi0 = (ty+1)*GP + (tx+1);
    const float4 gc = sg[gi0];

    float acc[CO];
    #pragma unroll
    for (int o = 0; o < CO; ++o) acc[o] = 0.f;

    #pragma unroll
    for (int k = 0; k < 9; ++k) {
        const int di = k/3 - 1, dj = k%3 - 1;
        float4 g4 = sg[gi0 + di*GP + dj];
        float d0 = g4.x - gc.x, d1 = g4.y - gc.y, d2 = g4.z - gc.z;
        float kern = __expf(-0.5f*(d0*d0 + d1*d1 + d2*d2));
        const int xo = ((((ty+di)>>1)+1)*XP + (((tx+dj)>>1)+1)) * NC4;
        #pragma unroll
        for (int o = 0; o < CO; ++o) {
            float s = 0.f;
            #pragma unroll
            for (int c4 = 0; c4 < NC4; ++c4) {
                float4 xv = sx[xo + c4];
                float4 wv = swt[(k*CO + o)*NC4 + c4];
                s += wv.x*xv.x + wv.y*xv.y + wv.z*xv.z + wv.w*xv.w;
            }
            acc[o] += kern * s;
        }
    }
    const int h = h0 + ty, w = w0 + tx;
    #pragma unroll
    for (int o = 0; o < CO; ++o) {
        float v = acc[o];
        v = (v >= 0.f) ? v : 0.01f*v;
        out[(b*CO + o)*HW + h*W + w] = v;
    }
}

// ============================================================================
// pac_pair: CI=4 mid stages. 128 threads; thread computes a 1x2 pair.
// Tile 32x8 outputs (8 rows x 16 pairs) -> 2x block count vs 32x16.
// ============================================================================
#define PTW 32
#define PTH 8
#define PGP (PTW+2)            // 34
#define PGT ((PTH+2)*PGP)      // 340
#define PXP (PTW/2+2)          // 18
#define PXT ((PTH/2+2)*PXP)    // 108

template<int CO, int ACT, int F>
__global__ __launch_bounds__(128) void pac_pair(
    const float* __restrict__ xin,    // (4,4,H/2,W/2)
    const float* __restrict__ guide,  // (4,3,512,512)
    const float* __restrict__ wt,     // (CO,4,3,3)
    float* __restrict__ out,          // (4,CO,H,W)
    int H, int W)
{
    __shared__ float4 sg[PGT];
    __shared__ float4 sx[PXT];
    __shared__ float4 swt[9*4];

    const int tid = threadIdx.x;
    const int b   = blockIdx.z;
    const int h0  = blockIdx.y * PTH;
    const int w0  = blockIdx.x * PTW;
    const int HW  = H*W;
    const int H2 = H >> 1, W2 = W >> 1, HW2 = H2*W2;

    const float* gb = guide + b*3*GSTRIDE;
    for (int i = tid; i < PGT; i += 128) {
        int r = i / PGP, q = i - r*PGP;
        sg[i] = fetch_guide<F>(gb, h0 - 1 + r, w0 - 1 + q, H, W);
    }
    const float* xb = xin + b*4*HW2;
    for (int i = tid; i < PXT; i += 128) {
        int r = i / PXP, q = i - r*PXP;
        int xh = (h0>>1) - 1 + r, xw = (w0>>1) - 1 + q;
        float4 v = make_float4(0.f, 0.f, 0.f, 0.f);
        if ((xh >= 0) & (xh < H2) & (xw >= 0) & (xw < W2)) {
            int off = xh*W2 + xw;
            const float* p = xb + off;
            v.x = p[0]; v.y = p[HW2]; v.z = p[2*HW2]; v.w = p[3*HW2];
        }
        sx[i] = v;
    }
    if (tid < 36) {
        int ci = tid & 3, k = tid >> 2;
        float4 v;
        v.x = wt[(0*4 + ci)*9 + k];
        v.y = wt[(1*4 + ci)*9 + k];
        v.z = wt[(2*4 + ci)*9 + k];
        v.w = wt[(3*4 + ci)*9 + k];
        swt[k*4 + ci] = v;
    }
    __syncthreads();

    const int ty = tid >> 4;          // 0..7 output row
    const int tx = tid & 15;          // pair index; cols 2*tx, 2*tx+1

    const int rb = ((ty-1)>>1) + 1;
    float4 xw[2][3];
    #pragma unroll
    for (int rr = 0; rr < 2; ++rr)
        #pragma unroll
        for (int cc = 0; cc < 3; ++cc)
            xw[rr][cc] = sx[(rb+rr)*PXP + (tx+cc)];
    const int midrow = 1 - (ty & 1);
    float4 xmid[3];
    #pragma unroll
    for (int cc = 0; cc < 3; ++cc) xmid[cc] = xw[midrow][cc];

    const int gi0 = (ty+1)*PGP + (2*tx+1);
    const float4 gq0 = sg[gi0];
    const float4 gq1 = sg[gi0 + 1];

    float4 acc4[2];
    acc4[0] = make_float4(0.f,0.f,0.f,0.f);
    acc4[1] = make_float4(0.f,0.f,0.f,0.f);

    #pragma unroll
    for (int k = 0; k < 9; ++k) {
        const int di = k/3 - 1, dj = k%3 - 1;
        float4 xv0, xv1;
        {
            const int cs0 = ((0+dj) >> 1) + 1;
            const int cs1 = ((1+dj) >> 1) + 1;
            if (di == -1)      { xv0 = xw[0][cs0]; xv1 = xw[0][cs1]; }
            else if (di == 1)  { xv0 = xw[1][cs0]; xv1 = xw[1][cs1]; }
            else               { xv0 = xmid[cs0];  xv1 = xmid[cs1];  }
        }
        float4 g0 = sg[gi0 + di*PGP + dj];
        float4 g1 = sg[gi0 + 1 + di*PGP + dj];
        float e0 = g0.x - gq0.x, e1 = g0.y - gq0.y, e2 = g0.z - gq0.z;
        float f0 = g1.x - gq1.x, f1 = g1.y - gq1.y, f2 = g1.z - gq1.z;
        float kern0 = __expf(-0.5f*(e0*e0 + e1*e1 + e2*e2));
        float kern1 = __expf(-0.5f*(f0*f0 + f1*f1 + f2*f2));

        float4 wv0 = swt[k*4+0], wv1 = swt[k*4+1], wv2 = swt[k*4+2], wv3 = swt[k*4+3];
        acc4[0].x += kern0*(xv0.x*wv0.x + xv0.y*wv1.x + xv0.z*wv2.x + xv0.w*wv3.x);
        acc4[0].y += kern0*(xv0.x*wv0.y + xv0.y*wv1.y + xv0.z*wv2.y + xv0.w*wv3.y);
        acc4[0].z += kern0*(xv0.x*wv0.z + xv0.y*wv1.z + xv0.z*wv2.z + xv0.w*wv3.z);
        acc4[0].w += kern0*(xv0.x*wv0.w + xv0.y*wv1.w + xv0.z*wv2.w + xv0.w*wv3.w);
        acc4[1].x += kern1*(xv1.x*wv0.x + xv1.y*wv1.x + xv1.z*wv2.x + xv1.w*wv3.x);
        acc4[1].y += kern1*(xv1.x*wv0.y + xv1.y*wv1.y + xv1.z*wv2.y + xv1.w*wv3.y);
        acc4[1].z += kern1*(xv1.x*wv0.z + xv1.y*wv1.z + xv1.z*wv2.z + xv1.w*wv3.z);
        acc4[1].w += kern1*(xv1.x*wv0.w + xv1.y*wv1.w + xv1.z*wv2.w + xv1.w*wv3.w);
    }

    const int h = h0 + ty, w = w0 + 2*tx;
    float* op = out + b*4*HW + h*W + w;
    #pragma unroll
    for (int p = 0; p < 2; ++p) {
        acc4[p].x = (acc4[p].x >= 0.f) ? acc4[p].x : 0.01f*acc4[p].x;
        acc4[p].y = (acc4[p].y >= 0.f) ? acc4[p].y : 0.01f*acc4[p].y;
        acc4[p].z = (acc4[p].z >= 0.f) ? acc4[p].z : 0.01f*acc4[p].z;
        acc4[p].w = (acc4[p].w >= 0.f) ? acc4[p].w : 0.01f*acc4[p].w;
    }
    *(float2*)(op)        = make_float2(acc4[0].x, acc4[1].x);
    *(float2*)(op + HW)   = make_float2(acc4[0].y, acc4[1].y);
    *(float2*)(op + 2*HW) = make_float2(acc4[0].z, acc4[1].z);
    *(float2*)(op + 3*HW) = make_float2(acc4[0].w, acc4[1].w);
}

// ============================================================================
// pac_quad: 512^2 final stage (CO=1, sigmoid). 128 threads; 2x2 quads.
// ============================================================================
#define QTW 32
#define QTH 16
#define QGP (QTW+2)
#define QGT ((QTH+2)*QGP)
#define QXP (QTW/2+2)
#define QXT ((QTH/2+2)*QXP)

template<int CO, int ACT, int F>
__global__ __launch_bounds__(128) void pac_quad(
    const float* __restrict__ xin,
    const float* __restrict__ guide,
    const float* __restrict__ wt,
    float* __restrict__ out,
    int H, int W)
{
    __shared__ float4 sg[QGT];
    __shared__ float4 sx[QXT];

    const int tid = threadIdx.x;
    const int b   = blockIdx.z;
    const int h0  = blockIdx.y * QTH;
    const int w0  = blockIdx.x * QTW;
    const int HW  = H*W;
    const int H2 = H >> 1, W2 = W >> 1, HW2 = H2*W2;

    const float* gb = guide + b*3*GSTRIDE;
    for (int i = tid; i < QGT; i += 128) {
        int r = i / QGP, q = i - r*QGP;
        sg[i] = fetch_guide<F>(gb, h0 - 1 + r, w0 - 1 + q, H, W);
    }
    const float* xb = xin + b*4*HW2;
    for (int i = tid; i < QXT; i += 128) {
        int r = i / QXP, q = i - r*QXP;
        int xh = (h0>>1) - 1 + r, xw = (w0>>1) - 1 + q;
        float4 v = make_float4(0.f, 0.f, 0.f, 0.f);
        if ((xh >= 0) & (xh < H2) & (xw >= 0) & (xw < W2)) {
            int off = xh*W2 + xw;
            const float* p = xb + off;
            v.x = p[0]; v.y = p[HW2]; v.z = p[2*HW2]; v.w = p[3*HW2];
        }
        sx[i] = v;
    }
    float4 wr[9];
    #pragma unroll
    for (int k = 0; k < 9; ++k) {
        float4 v;
        v.x = __ldg(wt + 0*9 + k);
        v.y = __ldg(wt + 1*9 + k);
        v.z = __ldg(wt + 2*9 + k);
        v.w = __ldg(wt + 3*9 + k);
        wr[k] = v;
    }
    __syncthreads();

    const int qy = tid >> 4;
    const int qx = tid & 15;

    float4 xw[9];
    #pragma unroll
    for (int rr = 0; rr < 3; ++rr)
        #pragma unroll
        for (int cc = 0; cc < 3; ++cc)
            xw[rr*3+cc] = sx[(qy+rr)*QXP + (qx+cc)];

    const int gbase = (2*qy+1)*QGP + (2*qx+1);
    float4 gq[4];
    gq[0] = sg[gbase];
    gq[1] = sg[gbase + 1];
    gq[2] = sg[gbase + QGP];
    gq[3] = sg[gbase + QGP + 1];

    float acc1[4] = {0.f, 0.f, 0.f, 0.f};

    #pragma unroll
    for (int k = 0; k < 9; ++k) {
        const int di = k/3 - 1, dj = k%3 - 1;
        #pragma unroll
        for (int p = 0; p < 4; ++p) {
            const int rr = p >> 1, cc = p & 1;
            float4 g4 = sg[gbase + (rr+di)*QGP + (cc+dj)];
            float d0 = g4.x - gq[p].x, d1 = g4.y - gq[p].y, d2 = g4.z - gq[p].z;
            float kern = __expf(-0.5f*(d0*d0 + d1*d1 + d2*d2));
            const int xr = (rr + di + 2) >> 1;
            const int xc = (cc + dj + 2) >> 1;
            float4 xv = xw[xr*3 + xc];
            float4 wv = wr[k];
            acc1[p] += kern*(xv.x*wv.x + xv.y*wv.y + xv.z*wv.z + xv.w*wv.w);
        }
    }

    const int h = h0 + 2*qy, w = w0 + 2*qx;
    #pragma unroll
    for (int p = 0; p < 4; ++p) {
        if (ACT == 1) acc1[p] = (acc1[p] >= 0.f) ? acc1[p] : 0.01f*acc1[p];
        else          acc1[p] = 1.0f / (1.0f + __expf(-acc1[p]));
    }
    float* op = out + b*HW + h*W + w;
    *(float2*)(op)     = make_float2(acc1[0], acc1[1]);
    *(float2*)(op + W) = make_float2(acc1[2], acc1[3]);
}

// ---------------- launch ----------------
extern "C" void kernel_launch(void* const* d_in, const int* in_sizes, int n_in,
                              void* d_out, int out_size)
{
    const float* x     = (const float*)d_in[0];
    const float* guide = (const float*)d_in[1];
    const float* lin_w = (const float*)d_in[2];
    const float* lin_b = (const float*)d_in[3];
    const float* w0    = (const float*)d_in[4];
    const float* w1    = (const float*)d_in[5];
    const float* w2    = (const float*)d_in[6];
    const float* w3    = (const float*)d_in[7];
    float* out = (float*)d_out;

    float *x0, *xa, *xb, *xc;
    cudaGetSymbolAddress((void**)&x0, g_x0);
    cudaGetSymbolAddress((void**)&xa, g_xa);
    cudaGetSymbolAddress((void**)&xb, g_xb);
    cudaGetSymbolAddress((void**)&xc, g_xc);

    lin_kernel<<<64, 256>>>(x, lin_w, lin_b, x0);

    pac_tile<16,4,8><<<dim3( 2,  8, 4), 256>>>(x0, guide, w0, xa,  64,  64);
    pac_pair<4,1,4><<<dim3( 4, 16, 4), 128>>>(xa, guide, w1, xb, 128, 128);
    pac_pair<4,1,2><<<dim3( 8, 32, 4), 128>>>(xb, guide, w2, xc, 256, 256);
    pac_quad<1,2,1><<<dim3(16, 32, 4), 128>>>(xc, guide, w3, out, 512, 512);
}